// round 4
// baseline (speedup 1.0000x reference)
#include <cuda_runtime.h>
#include <cuda_bf16.h>
#include <math.h>

// Problem constants (match reference)
#define NN 50000
#define EE 800000
#define ET (EE + NN)      // edges + self loops = 850000
#define DD 128            // gnn dim
#define HH 256            // mlp hidden
#define CC 6              // labels

// ---------------- scratch (device globals; no runtime allocation) -----------
__device__ float g_h0[(size_t)NN * DD];     // projected h (per layer)
__device__ float g_h1[(size_t)NN * DD];     // layer output / next input
__device__ float g_hid[(size_t)NN * HH];    // mlp hidden
__device__ float g_ssrc[NN];
__device__ float g_sdst[NN];
__device__ int   g_src[ET];
__device__ int   g_dst[ET];
__device__ int   g_srcs[ET];                // src sorted by dst segment
__device__ int   g_deg[NN];
__device__ int   g_offs[NN + 1];
__device__ int   g_fill[NN];
__device__ int   g_is64;

// ---------------- edge-index dtype detection --------------------------------
// Values are < 50000, so if the buffer is int64 every odd 32-bit word is 0.
__global__ void detect_k(const unsigned int* __restrict__ w) {
    __shared__ int any;
    if (threadIdx.x == 0) any = 0;
    __syncthreads();
    int t = 0;
    for (int i = threadIdx.x; i < 1024; i += blockDim.x)
        t |= (w[2 * i + 1] != 0u);
    if (t) any = 1;
    __syncthreads();
    if (threadIdx.x == 0) g_is64 = any ? 0 : 1;
}

__global__ void init_k() {
    int i = blockIdx.x * blockDim.x + threadIdx.x;
    if (i < NN) { g_deg[i] = 0; g_fill[i] = 0; }
}

// Convert edge list (+ self loops), count in-degrees.
__global__ void build_k(const void* __restrict__ ei) {
    int i = blockIdx.x * blockDim.x + threadIdx.x;
    if (i >= ET) return;
    int s, d;
    if (i < EE) {
        if (g_is64) {
            const long long* p = (const long long*)ei;
            s = (int)p[i]; d = (int)p[EE + i];
        } else {
            const int* p = (const int*)ei;
            s = p[i]; d = p[EE + i];
        }
    } else {
        s = d = i - EE;   // self loop
    }
    g_src[i] = s; g_dst[i] = d;
    atomicAdd(&g_deg[d], 1);
}

// Single-block chunked Hillis-Steele scan: offs = exclusive_scan(deg)
__global__ void scan_k() {
    __shared__ int sh[1024];
    __shared__ int carry_s;
    int tid = threadIdx.x;
    if (tid == 0) carry_s = 0;
    __syncthreads();
    for (int base = 0; base < NN; base += 1024) {
        int i = base + tid;
        int v = (i < NN) ? g_deg[i] : 0;
        sh[tid] = v;
        __syncthreads();
        for (int off = 1; off < 1024; off <<= 1) {
            int t = (tid >= off) ? sh[tid - off] : 0;
            __syncthreads();
            sh[tid] += t;
            __syncthreads();
        }
        if (i < NN) g_offs[i + 1] = carry_s + sh[tid];
        __syncthreads();
        if (tid == 0) carry_s += sh[1023];
        __syncthreads();
    }
    if (tid == 0) g_offs[0] = 0;
}

// Bucket srcs by dst segment.
__global__ void scatter_k() {
    int i = blockIdx.x * blockDim.x + threadIdx.x;
    if (i >= ET) return;
    int d = g_dst[i];
    int pos = g_offs[d] + atomicAdd(&g_fill[d], 1);
    g_srcs[pos] = g_src[i];
}

// ---------------- SGEMM: C[nrows,M] = A[nrows,K] @ B[K,M] (+bias, relu) -----
// BM=128, BN=128, BK=8, 256 threads, 8x8 microtile per thread.
__global__ __launch_bounds__(256) void sgemm_k(
    const float* __restrict__ A, const float* __restrict__ B,
    const float* __restrict__ bias, float* __restrict__ C,
    int nrows, int K, int M, int doRelu)
{
    __shared__ float As[8][128];
    __shared__ float Bs[8][128];
    int brow = blockIdx.x * 128;
    int bcol = blockIdx.y * 128;
    int tid  = threadIdx.x;
    int tr   = (tid / 16) * 8;
    int tc   = (tid % 16) * 8;

    float acc[8][8];
#pragma unroll
    for (int i = 0; i < 8; i++)
#pragma unroll
        for (int j = 0; j < 8; j++) acc[i][j] = 0.f;

    int arow = tid >> 1;          // 0..127
    int akk  = (tid & 1) * 4;     // 0 or 4
    int bkk  = tid >> 5;          // 0..7
    int bcc  = (tid & 31) * 4;    // 0..124

    for (int k0 = 0; k0 < K; k0 += 8) {
        float4 av = make_float4(0.f, 0.f, 0.f, 0.f);
        int gr = brow + arow;
        if (gr < nrows)
            av = *(const float4*)(A + (size_t)gr * K + k0 + akk);
        As[akk + 0][arow] = av.x; As[akk + 1][arow] = av.y;
        As[akk + 2][arow] = av.z; As[akk + 3][arow] = av.w;

        float4 bv = *(const float4*)(B + (size_t)(k0 + bkk) * M + bcol + bcc);
        *(float4*)&Bs[bkk][bcc] = bv;
        __syncthreads();

#pragma unroll
        for (int kk = 0; kk < 8; kk++) {
            float af[8], bf[8];
#pragma unroll
            for (int i = 0; i < 8; i++) af[i] = As[kk][tr + i];
#pragma unroll
            for (int j = 0; j < 8; j++) bf[j] = Bs[kk][tc + j];
#pragma unroll
            for (int i = 0; i < 8; i++)
#pragma unroll
                for (int j = 0; j < 8; j++)
                    acc[i][j] = fmaf(af[i], bf[j], acc[i][j]);
        }
        __syncthreads();
    }

#pragma unroll
    for (int i = 0; i < 8; i++) {
        int gr = brow + tr + i;
        if (gr < nrows) {
#pragma unroll
            for (int j = 0; j < 8; j += 4) {
                float4 v = make_float4(acc[i][j], acc[i][j+1], acc[i][j+2], acc[i][j+3]);
                if (bias) {
                    const float4 bb = *(const float4*)(bias + bcol + tc + j);
                    v.x += bb.x; v.y += bb.y; v.z += bb.z; v.w += bb.w;
                }
                if (doRelu) {
                    v.x = fmaxf(v.x, 0.f); v.y = fmaxf(v.y, 0.f);
                    v.z = fmaxf(v.z, 0.f); v.w = fmaxf(v.w, 0.f);
                }
                *(float4*)(C + (size_t)gr * M + bcol + tc + j) = v;
            }
        }
    }
}

// ---------------- per-node attention scalars: ssrc = h·a_src, sdst = h·a_dst
__global__ void dots_k(const float* __restrict__ h,
                       const float* __restrict__ a1,
                       const float* __restrict__ a2)
{
    int node = blockIdx.x * 8 + (threadIdx.x >> 5);
    int lane = threadIdx.x & 31;
    if (node >= NN) return;
    float4 hv = *(const float4*)(h + (size_t)node * DD + lane * 4);
    float4 s1 = *(const float4*)(a1 + lane * 4);
    float4 s2 = *(const float4*)(a2 + lane * 4);
    float p = hv.x * s1.x + hv.y * s1.y + hv.z * s1.z + hv.w * s1.w;
    float q = hv.x * s2.x + hv.y * s2.y + hv.z * s2.z + hv.w * s2.w;
#pragma unroll
    for (int o = 16; o > 0; o >>= 1) {
        p += __shfl_xor_sync(0xffffffffu, p, o);
        q += __shfl_xor_sync(0xffffffffu, q, o);
    }
    if (lane == 0) { g_ssrc[node] = p; g_sdst[node] = q; }
}

// ---------------- warp-per-dst-node segment softmax + weighted aggregate ----
__global__ void gat_agg_k(const float* __restrict__ h,
                          const float* __restrict__ bias,
                          float* __restrict__ out)
{
    int node = blockIdx.x * 8 + (threadIdx.x >> 5);
    int lane = threadIdx.x & 31;
    if (node >= NN) return;

    int beg = g_offs[node], end = g_offs[node + 1];
    float sd = g_sdst[node];

    // pass 1: max
    float mx = -3.4e38f;
    for (int e = beg + lane; e < end; e += 32) {
        float sc = g_ssrc[g_srcs[e]] + sd;
        sc = sc > 0.f ? sc : 0.2f * sc;
        mx = fmaxf(mx, sc);
    }
#pragma unroll
    for (int o = 16; o > 0; o >>= 1)
        mx = fmaxf(mx, __shfl_xor_sync(0xffffffffu, mx, o));

    // pass 2: sum of exp
    float sum = 0.f;
    for (int e = beg + lane; e < end; e += 32) {
        float sc = g_ssrc[g_srcs[e]] + sd;
        sc = sc > 0.f ? sc : 0.2f * sc;
        sum += __expf(sc - mx);
    }
#pragma unroll
    for (int o = 16; o > 0; o >>= 1)
        sum += __shfl_xor_sync(0xffffffffu, sum, o);
    float inv = 1.f / sum;

    // pass 3: weighted row aggregation (full warp per edge, 4 floats/lane)
    float4 acc = make_float4(0.f, 0.f, 0.f, 0.f);
    for (int e = beg; e < end; e++) {
        int sv = g_srcs[e];
        float sc = g_ssrc[sv] + sd;            // broadcast L1 hit
        sc = sc > 0.f ? sc : 0.2f * sc;
        float w = __expf(sc - mx) * inv;
        float4 hv = *(const float4*)(h + (size_t)sv * DD + lane * 4);
        acc.x = fmaf(hv.x, w, acc.x);
        acc.y = fmaf(hv.y, w, acc.y);
        acc.z = fmaf(hv.z, w, acc.z);
        acc.w = fmaf(hv.w, w, acc.w);
    }

    float4 bv = *(const float4*)(bias + lane * 4);
    acc.x = fmaxf(acc.x + bv.x, 0.f);
    acc.y = fmaxf(acc.y + bv.y, 0.f);
    acc.z = fmaxf(acc.z + bv.z, 0.f);
    acc.w = fmaxf(acc.w + bv.w, 0.f);
    *(float4*)(out + (size_t)node * DD + lane * 4) = acc;
}

// ---------------- final tiny GEMM: out[N,6] = hid[N,256] @ Wm2 + bm2 --------
__global__ void mlp2_k(const float* __restrict__ hid,
                       const float* __restrict__ W,
                       const float* __restrict__ b,
                       float* __restrict__ out)
{
    int node = blockIdx.x * 8 + (threadIdx.x >> 5);
    int lane = threadIdx.x & 31;
    if (node >= NN) return;
    float acc[CC];
#pragma unroll
    for (int c = 0; c < CC; c++) acc[c] = 0.f;
#pragma unroll
    for (int i = 0; i < HH / 32; i++) {
        int k = lane + i * 32;
        float v = hid[(size_t)node * HH + k];
#pragma unroll
        for (int c = 0; c < CC; c++)
            acc[c] = fmaf(v, W[k * CC + c], acc[c]);
    }
#pragma unroll
    for (int c = 0; c < CC; c++) {
#pragma unroll
        for (int o = 16; o > 0; o >>= 1)
            acc[c] += __shfl_xor_sync(0xffffffffu, acc[c], o);
    }
    if (lane == 0) {
#pragma unroll
        for (int c = 0; c < CC; c++)
            out[(size_t)node * CC + c] = acc[c] + b[c];
    }
}

// ---------------- host launch ------------------------------------------------
static void* symaddr(const void* s) {
    void* p = nullptr;
    cudaGetSymbolAddress(&p, s);
    return p;
}

extern "C" void kernel_launch(void* const* d_in, const int* in_sizes, int n_in,
                              void* d_out, int out_size)
{
    const float* x   = (const float*)d_in[0];
    const void*  ei  = d_in[1];
    const float* W[3]  = { (const float*)d_in[2],  (const float*)d_in[6],  (const float*)d_in[10] };
    const float* b[3]  = { (const float*)d_in[3],  (const float*)d_in[7],  (const float*)d_in[11] };
    const float* as_[3]= { (const float*)d_in[4],  (const float*)d_in[8],  (const float*)d_in[12] };
    const float* ad_[3]= { (const float*)d_in[5],  (const float*)d_in[9],  (const float*)d_in[13] };
    const float* Wm1 = (const float*)d_in[14];
    const float* bm1 = (const float*)d_in[15];
    const float* Wm2 = (const float*)d_in[16];
    const float* bm2 = (const float*)d_in[17];
    float* out = (float*)d_out;

    float* h0  = (float*)symaddr(g_h0);
    float* h1  = (float*)symaddr(g_h1);
    float* hid = (float*)symaddr(g_hid);

    // ---- graph preprocessing (shared by all 3 layers) ----
    detect_k<<<1, 256>>>((const unsigned int*)ei);
    init_k<<<(NN + 255) / 256, 256>>>();
    build_k<<<(ET + 255) / 256, 256>>>(ei);
    scan_k<<<1, 1024>>>();
    scatter_k<<<(ET + 255) / 256, 256>>>();

    // ---- 3 GAT layers ----
    const float* cur = x;
    for (int l = 0; l < 3; l++) {
        sgemm_k<<<dim3((NN + 127) / 128, 1), 256>>>(cur, W[l], nullptr, h0, NN, DD, DD, 0);
        dots_k<<<(NN + 7) / 8, 256>>>(h0, as_[l], ad_[l]);
        gat_agg_k<<<(NN + 7) / 8, 256>>>(h0, b[l], h1);
        cur = h1;
    }

    // ---- MLP head ----
    sgemm_k<<<dim3((NN + 127) / 128, 2), 256>>>(h1, Wm1, bm1, hid, NN, DD, HH, 1);
    mlp2_k<<<(NN + 7) / 8, 256>>>(hid, Wm2, bm2, out);
}

// round 5
// speedup vs baseline: 1.0940x; 1.0940x over previous
#include <cuda_runtime.h>
#include <cuda_bf16.h>
#include <math.h>

// Problem constants (match reference)
#define NN 50000
#define EE 800000
#define ET (EE + NN)      // edges + self loops = 850000
#define DD 128            // gnn dim
#define HH 256            // mlp hidden
#define CC 6              // labels

// ---------------- scratch (device globals; no runtime allocation) -----------
__device__ float g_h0[(size_t)NN * DD];     // projected h (per layer)
__device__ float g_h1[(size_t)NN * DD];     // layer output / next input
__device__ float g_hid[(size_t)NN * HH];    // mlp hidden
__device__ float g_ssrc[NN];
__device__ float g_sdst[NN];
__device__ int   g_src[ET];
__device__ int   g_dst[ET];
__device__ int   g_srcs[ET];                // src sorted by dst segment
__device__ int   g_deg[NN];
__device__ int   g_offs[NN + 1];
__device__ int   g_fill[NN];
__device__ int   g_is64;

// ---------------- edge-index dtype detection --------------------------------
// Values are < 50000, so if the buffer is int64 every odd 32-bit word is 0.
__global__ void detect_k(const unsigned int* __restrict__ w) {
    __shared__ int any;
    if (threadIdx.x == 0) any = 0;
    __syncthreads();
    int t = 0;
    for (int i = threadIdx.x; i < 1024; i += blockDim.x)
        t |= (w[2 * i + 1] != 0u);
    if (t) any = 1;
    __syncthreads();
    if (threadIdx.x == 0) g_is64 = any ? 0 : 1;
}

__global__ void init_k() {
    int i = blockIdx.x * blockDim.x + threadIdx.x;
    if (i < NN) { g_deg[i] = 0; g_fill[i] = 0; }
}

// Convert edge list (+ self loops), count in-degrees.
__global__ void build_k(const void* __restrict__ ei) {
    int i = blockIdx.x * blockDim.x + threadIdx.x;
    if (i >= ET) return;
    int s, d;
    if (i < EE) {
        if (g_is64) {
            const long long* p = (const long long*)ei;
            s = (int)p[i]; d = (int)p[EE + i];
        } else {
            const int* p = (const int*)ei;
            s = p[i]; d = p[EE + i];
        }
    } else {
        s = d = i - EE;   // self loop
    }
    g_src[i] = s; g_dst[i] = d;
    atomicAdd(&g_deg[d], 1);
}

// Fast single-block exclusive scan: 1024 threads, 49 elements/thread,
// thread-sequential partials + shfl warp scan (3 barriers total).
__global__ void scan_k() {
    const int PER = 49;                      // 1024*49 = 50176 >= NN
    __shared__ int warp_sums[32];
    int tid  = threadIdx.x;
    int lane = tid & 31;
    int wid  = tid >> 5;
    int base = tid * PER;

    int loc[PER];
    int s = 0;
#pragma unroll
    for (int i = 0; i < PER; i++) {
        int idx = base + i;
        int v = (idx < NN) ? g_deg[idx] : 0;
        loc[i] = s;                          // exclusive within-thread prefix
        s += v;
    }

    // inclusive warp scan of per-thread sums
    int inc = s;
#pragma unroll
    for (int o = 1; o < 32; o <<= 1) {
        int t = __shfl_up_sync(0xffffffffu, inc, o);
        if (lane >= o) inc += t;
    }
    if (lane == 31) warp_sums[wid] = inc;
    __syncthreads();
    if (wid == 0) {
        int w = warp_sums[lane];
#pragma unroll
        for (int o = 1; o < 32; o <<= 1) {
            int t = __shfl_up_sync(0xffffffffu, w, o);
            if (lane >= o) w += t;
        }
        warp_sums[lane] = w;                 // inclusive scan of warp sums
    }
    __syncthreads();

    int excl = inc - s + (wid ? warp_sums[wid - 1] : 0);
#pragma unroll
    for (int i = 0; i < PER; i++) {
        int idx = base + i;
        if (idx < NN) g_offs[idx] = excl + loc[i];
    }
    if (tid == 0) g_offs[NN] = ET;           // total is statically known
}

// Bucket srcs by dst segment.
__global__ void scatter_k() {
    int i = blockIdx.x * blockDim.x + threadIdx.x;
    if (i >= ET) return;
    int d = g_dst[i];
    int pos = g_offs[d] + atomicAdd(&g_fill[d], 1);
    g_srcs[pos] = g_src[i];
}

// ---------------- SGEMM: C[nrows,M] = A[nrows,K] @ B[K,M] (+bias, relu) -----
// BM=128, BN=128, BK=8, 256 threads, 8x8 microtile per thread.
// If asrc != nullptr (layer GEMMs, M==128, grid.y==1): fuse the per-row
// attention dot products ssrc = C·asrc, sdst = C·adst into the epilogue.
__global__ __launch_bounds__(256) void sgemm_k(
    const float* __restrict__ A, const float* __restrict__ B,
    const float* __restrict__ bias, float* __restrict__ C,
    int nrows, int K, int M, int doRelu,
    const float* __restrict__ asrc, const float* __restrict__ adst,
    float* __restrict__ ssrc_out, float* __restrict__ sdst_out)
{
    __shared__ float As[8][128];
    __shared__ float Bs[8][128];
    int brow = blockIdx.x * 128;
    int bcol = blockIdx.y * 128;
    int tid  = threadIdx.x;
    int tr   = (tid / 16) * 8;
    int tc   = (tid % 16) * 8;

    float acc[8][8];
#pragma unroll
    for (int i = 0; i < 8; i++)
#pragma unroll
        for (int j = 0; j < 8; j++) acc[i][j] = 0.f;

    int arow = tid >> 1;          // 0..127
    int akk  = (tid & 1) * 4;     // 0 or 4
    int bkk  = tid >> 5;          // 0..7
    int bcc  = (tid & 31) * 4;    // 0..124

    for (int k0 = 0; k0 < K; k0 += 8) {
        float4 av = make_float4(0.f, 0.f, 0.f, 0.f);
        int gr = brow + arow;
        if (gr < nrows)
            av = *(const float4*)(A + (size_t)gr * K + k0 + akk);
        As[akk + 0][arow] = av.x; As[akk + 1][arow] = av.y;
        As[akk + 2][arow] = av.z; As[akk + 3][arow] = av.w;

        float4 bv = *(const float4*)(B + (size_t)(k0 + bkk) * M + bcol + bcc);
        *(float4*)&Bs[bkk][bcc] = bv;
        __syncthreads();

#pragma unroll
        for (int kk = 0; kk < 8; kk++) {
            float af[8], bf[8];
#pragma unroll
            for (int i = 0; i < 8; i++) af[i] = As[kk][tr + i];
#pragma unroll
            for (int j = 0; j < 8; j++) bf[j] = Bs[kk][tc + j];
#pragma unroll
            for (int i = 0; i < 8; i++)
#pragma unroll
                for (int j = 0; j < 8; j++)
                    acc[i][j] = fmaf(af[i], bf[j], acc[i][j]);
        }
        __syncthreads();
    }

    // ---- fused attention dots (layer GEMMs only; bias==null, no relu) ----
    if (asrc) {
        float as[8], ad[8];
#pragma unroll
        for (int j = 0; j < 8; j++) { as[j] = asrc[tc + j]; ad[j] = adst[tc + j]; }
        int lane16 = tid & 15;
#pragma unroll
        for (int i = 0; i < 8; i++) {
            float ps = 0.f, pd = 0.f;
#pragma unroll
            for (int j = 0; j < 8; j++) {
                ps = fmaf(acc[i][j], as[j], ps);
                pd = fmaf(acc[i][j], ad[j], pd);
            }
            // reduce across the 16 lanes that share this row (tid%16 = col group)
#pragma unroll
            for (int o = 8; o > 0; o >>= 1) {
                ps += __shfl_xor_sync(0xffffffffu, ps, o);
                pd += __shfl_xor_sync(0xffffffffu, pd, o);
            }
            if (lane16 == 0) {
                int gr = brow + tr + i;
                if (gr < nrows) { ssrc_out[gr] = ps; sdst_out[gr] = pd; }
            }
        }
    }

#pragma unroll
    for (int i = 0; i < 8; i++) {
        int gr = brow + tr + i;
        if (gr < nrows) {
#pragma unroll
            for (int j = 0; j < 8; j += 4) {
                float4 v = make_float4(acc[i][j], acc[i][j+1], acc[i][j+2], acc[i][j+3]);
                if (bias) {
                    const float4 bb = *(const float4*)(bias + bcol + tc + j);
                    v.x += bb.x; v.y += bb.y; v.z += bb.z; v.w += bb.w;
                }
                if (doRelu) {
                    v.x = fmaxf(v.x, 0.f); v.y = fmaxf(v.y, 0.f);
                    v.z = fmaxf(v.z, 0.f); v.w = fmaxf(v.w, 0.f);
                }
                *(float4*)(C + (size_t)gr * M + bcol + tc + j) = v;
            }
        }
    }
}

// ---------------- warp-per-dst-node segment softmax + weighted aggregate ----
__global__ void gat_agg_k(const float* __restrict__ h,
                          const float* __restrict__ bias,
                          float* __restrict__ out)
{
    int node = blockIdx.x * 8 + (threadIdx.x >> 5);
    int lane = threadIdx.x & 31;
    if (node >= NN) return;

    int beg = g_offs[node], end = g_offs[node + 1];
    float sd = g_sdst[node];

    // pass 1: max
    float mx = -3.4e38f;
    for (int e = beg + lane; e < end; e += 32) {
        float sc = g_ssrc[g_srcs[e]] + sd;
        sc = sc > 0.f ? sc : 0.2f * sc;
        mx = fmaxf(mx, sc);
    }
#pragma unroll
    for (int o = 16; o > 0; o >>= 1)
        mx = fmaxf(mx, __shfl_xor_sync(0xffffffffu, mx, o));

    // pass 2: sum of exp
    float sum = 0.f;
    for (int e = beg + lane; e < end; e += 32) {
        float sc = g_ssrc[g_srcs[e]] + sd;
        sc = sc > 0.f ? sc : 0.2f * sc;
        sum += __expf(sc - mx);
    }
#pragma unroll
    for (int o = 16; o > 0; o >>= 1)
        sum += __shfl_xor_sync(0xffffffffu, sum, o);
    float inv = 1.f / sum;

    // pass 3: weighted row aggregation (full warp per edge, 4 floats/lane)
    float4 acc = make_float4(0.f, 0.f, 0.f, 0.f);
    for (int e = beg; e < end; e++) {
        int sv = g_srcs[e];
        float sc = g_ssrc[sv] + sd;            // broadcast L1 hit
        sc = sc > 0.f ? sc : 0.2f * sc;
        float w = __expf(sc - mx) * inv;
        float4 hv = *(const float4*)(h + (size_t)sv * DD + lane * 4);
        acc.x = fmaf(hv.x, w, acc.x);
        acc.y = fmaf(hv.y, w, acc.y);
        acc.z = fmaf(hv.z, w, acc.z);
        acc.w = fmaf(hv.w, w, acc.w);
    }

    float4 bv = *(const float4*)(bias + lane * 4);
    acc.x = fmaxf(acc.x + bv.x, 0.f);
    acc.y = fmaxf(acc.y + bv.y, 0.f);
    acc.z = fmaxf(acc.z + bv.z, 0.f);
    acc.w = fmaxf(acc.w + bv.w, 0.f);
    *(float4*)(out + (size_t)node * DD + lane * 4) = acc;
}

// ---------------- final tiny GEMM: out[N,6] = hid[N,256] @ Wm2 + bm2 --------
__global__ void mlp2_k(const float* __restrict__ hid,
                       const float* __restrict__ W,
                       const float* __restrict__ b,
                       float* __restrict__ out)
{
    int node = blockIdx.x * 8 + (threadIdx.x >> 5);
    int lane = threadIdx.x & 31;
    if (node >= NN) return;
    float acc[CC];
#pragma unroll
    for (int c = 0; c < CC; c++) acc[c] = 0.f;
#pragma unroll
    for (int i = 0; i < HH / 32; i++) {
        int k = lane + i * 32;
        float v = hid[(size_t)node * HH + k];
#pragma unroll
        for (int c = 0; c < CC; c++)
            acc[c] = fmaf(v, W[k * CC + c], acc[c]);
    }
#pragma unroll
    for (int c = 0; c < CC; c++) {
#pragma unroll
        for (int o = 16; o > 0; o >>= 1)
            acc[c] += __shfl_xor_sync(0xffffffffu, acc[c], o);
    }
    if (lane == 0) {
#pragma unroll
        for (int c = 0; c < CC; c++)
            out[(size_t)node * CC + c] = acc[c] + b[c];
    }
}

// ---------------- host launch ------------------------------------------------
static void* symaddr(const void* s) {
    void* p = nullptr;
    cudaGetSymbolAddress(&p, s);
    return p;
}

extern "C" void kernel_launch(void* const* d_in, const int* in_sizes, int n_in,
                              void* d_out, int out_size)
{
    const float* x   = (const float*)d_in[0];
    const void*  ei  = d_in[1];
    const float* W[3]  = { (const float*)d_in[2],  (const float*)d_in[6],  (const float*)d_in[10] };
    const float* b[3]  = { (const float*)d_in[3],  (const float*)d_in[7],  (const float*)d_in[11] };
    const float* as_[3]= { (const float*)d_in[4],  (const float*)d_in[8],  (const float*)d_in[12] };
    const float* ad_[3]= { (const float*)d_in[5],  (const float*)d_in[9],  (const float*)d_in[13] };
    const float* Wm1 = (const float*)d_in[14];
    const float* bm1 = (const float*)d_in[15];
    const float* Wm2 = (const float*)d_in[16];
    const float* bm2 = (const float*)d_in[17];
    float* out = (float*)d_out;

    float* h0  = (float*)symaddr(g_h0);
    float* h1  = (float*)symaddr(g_h1);
    float* hid = (float*)symaddr(g_hid);
    float* ssrc = (float*)symaddr(g_ssrc);
    float* sdst = (float*)symaddr(g_sdst);

    // ---- graph preprocessing (shared by all 3 layers) ----
    detect_k<<<1, 256>>>((const unsigned int*)ei);
    init_k<<<(NN + 255) / 256, 256>>>();
    build_k<<<(ET + 255) / 256, 256>>>(ei);
    scan_k<<<1, 1024>>>();
    scatter_k<<<(ET + 255) / 256, 256>>>();

    // ---- 3 GAT layers (attention dots fused into GEMM epilogue) ----
    const float* cur = x;
    for (int l = 0; l < 3; l++) {
        sgemm_k<<<dim3((NN + 127) / 128, 1), 256>>>(
            cur, W[l], nullptr, h0, NN, DD, DD, 0,
            as_[l], ad_[l], ssrc, sdst);
        gat_agg_k<<<(NN + 7) / 8, 256>>>(h0, b[l], h1);
        cur = h1;
    }

    // ---- MLP head ----
    sgemm_k<<<dim3((NN + 127) / 128, 2), 256>>>(
        h1, Wm1, bm1, hid, NN, DD, HH, 1,
        nullptr, nullptr, nullptr, nullptr);
    mlp2_k<<<(NN + 7) / 8, 256>>>(hid, Wm2, bm2, out);
}

// round 6
// speedup vs baseline: 1.1376x; 1.0399x over previous
#include <cuda_runtime.h>
#include <cuda_bf16.h>
#include <math.h>

// Problem constants (match reference)
#define NN 50000
#define EE 800000
#define ET (EE + NN)      // edges + self loops = 850000
#define DD 128            // gnn dim
#define HH 256            // mlp hidden
#define CC 6              // labels
#define NB ((NN + 1023) / 1024)   // 49 scan blocks

// ---------------- scratch (device globals; no runtime allocation) -----------
__device__ float g_h0[(size_t)NN * DD];     // projected h (per layer)
__device__ float g_h1[(size_t)NN * DD];     // layer output / next input
__device__ float g_hid[(size_t)NN * HH];    // mlp hidden
__device__ float g_ssrc[NN];
__device__ float g_sdst[NN];
__device__ int   g_src[ET];
__device__ int   g_dst[ET];
__device__ int   g_srcs[ET];                // src sorted by dst segment
__device__ int   g_deg[NN];
__device__ int   g_offs[NN + 1];
__device__ int   g_fill[NN];
__device__ int   g_bsum[64];
__device__ int   g_is64;

// ---------------- edge-index dtype detection --------------------------------
// Values are < 50000, so if the buffer is int64 every odd 32-bit word is 0.
__global__ void detect_k(const unsigned int* __restrict__ w) {
    __shared__ int any;
    if (threadIdx.x == 0) any = 0;
    __syncthreads();
    int t = 0;
    for (int i = threadIdx.x; i < 1024; i += blockDim.x)
        t |= (w[2 * i + 1] != 0u);
    if (t) any = 1;
    __syncthreads();
    if (threadIdx.x == 0) g_is64 = any ? 0 : 1;
}

__global__ void init_k() {
    int i = blockIdx.x * blockDim.x + threadIdx.x;
    if (i < NN) { g_deg[i] = 0; g_fill[i] = 0; }
}

// Convert edge list (+ self loops), count in-degrees.
__global__ void build_k(const void* __restrict__ ei) {
    int i = blockIdx.x * blockDim.x + threadIdx.x;
    if (i >= ET) return;
    int s, d;
    if (i < EE) {
        if (g_is64) {
            const long long* p = (const long long*)ei;
            s = (int)p[i]; d = (int)p[EE + i];
        } else {
            const int* p = (const int*)ei;
            s = p[i]; d = p[EE + i];
        }
    } else {
        s = d = i - EE;   // self loop
    }
    g_src[i] = s; g_dst[i] = d;
    atomicAdd(&g_deg[d], 1);
}

// ---------------- 3-phase coalesced exclusive scan of g_deg -> g_offs -------
// Phase 1: per-block (1024 elems) exclusive scan + block total.
__global__ void scan1_k() {
    __shared__ int wsum[32];
    int b = blockIdx.x, tid = threadIdx.x;
    int i = b * 1024 + tid;
    int v = (i < NN) ? g_deg[i] : 0;
    int lane = tid & 31, wid = tid >> 5;

    int inc = v;
#pragma unroll
    for (int o = 1; o < 32; o <<= 1) {
        int t = __shfl_up_sync(0xffffffffu, inc, o);
        if (lane >= o) inc += t;
    }
    if (lane == 31) wsum[wid] = inc;
    __syncthreads();
    if (wid == 0) {
        int w = wsum[lane];
#pragma unroll
        for (int o = 1; o < 32; o <<= 1) {
            int t = __shfl_up_sync(0xffffffffu, w, o);
            if (lane >= o) w += t;
        }
        wsum[lane] = w;
    }
    __syncthreads();
    int excl = inc - v + (wid ? wsum[wid - 1] : 0);
    if (i < NN) g_offs[i] = excl;
    if (tid == 1023) g_bsum[b] = excl + v;      // block total
}

// Phase 2: single warp scans the 49 block totals (exclusive, in place).
__global__ void scan2_k() {
    int lane = threadIdx.x;       // 32 threads
    int v0 = (lane < NB) ? g_bsum[lane] : 0;
    int a = v0;
#pragma unroll
    for (int o = 1; o < 32; o <<= 1) {
        int t = __shfl_up_sync(0xffffffffu, a, o);
        if (lane >= o) a += t;
    }
    int tot32 = __shfl_sync(0xffffffffu, a, 31);
    int v1 = (lane + 32 < NB) ? g_bsum[lane + 32] : 0;
    int c = v1;
#pragma unroll
    for (int o = 1; o < 32; o <<= 1) {
        int t = __shfl_up_sync(0xffffffffu, c, o);
        if (lane >= o) c += t;
    }
    g_bsum[lane] = a - v0;                       // exclusive
    g_bsum[lane + 32] = (c - v1) + tot32;
}

// Phase 3: add block offsets.
__global__ void scan3_k() {
    int i = blockIdx.x * blockDim.x + threadIdx.x;
    if (i < NN) g_offs[i] += g_bsum[i >> 10];
    if (i == 0) g_offs[NN] = ET;
}

// Bucket srcs by dst segment.
__global__ void scatter_k() {
    int i = blockIdx.x * blockDim.x + threadIdx.x;
    if (i >= ET) return;
    int d = g_dst[i];
    int pos = g_offs[d] + atomicAdd(&g_fill[d], 1);
    g_srcs[pos] = g_src[i];
}

// ---------------- SGEMM: C[nrows,M] = A[nrows,K] @ B[K,M] (+bias, relu) -----
// BM=128, BN=128, BK=16, 256 threads, 8x8 microtile, double-buffered smem,
// register prefetch, 1 barrier per k-iteration. K must be a multiple of 16.
// If asrc != nullptr (layer GEMMs, M==128): fuse per-row attention dots
// ssrc = C·asrc, sdst = C·adst into the epilogue.
__global__ __launch_bounds__(256) void sgemm_k(
    const float* __restrict__ A, const float* __restrict__ B,
    const float* __restrict__ bias, float* __restrict__ C,
    int nrows, int K, int M, int doRelu,
    const float* __restrict__ asrc, const float* __restrict__ adst,
    float* __restrict__ ssrc_out, float* __restrict__ sdst_out)
{
    __shared__ float As[2][16][128];
    __shared__ float Bs[2][16][128];
    int brow = blockIdx.x * 128;
    int bcol = blockIdx.y * 128;
    int tid  = threadIdx.x;
    int tr   = (tid / 16) * 8;
    int tc   = (tid % 16) * 8;

    // A-tile mapping: 128 rows x 16 k. thread -> row = tid&127, k = (tid>>7)*8
    int a_r = tid & 127;
    int a_k = (tid >> 7) * 8;
    int gr_a = brow + a_r;
    bool a_ok = gr_a < nrows;
    const float* Ap = A + (size_t)gr_a * K + a_k;

    // B-tile mapping: 16 rows x 128 cols. thread -> row = tid>>4, col = (tid&15)*8
    int b_r = tid >> 4;
    int b_c = (tid & 15) * 8;
    const float* Bp = B + (size_t)b_r * M + bcol + b_c;

    const float4 z4 = make_float4(0.f, 0.f, 0.f, 0.f);
    float4 a0, a1, b0, b1;

    // load tile 0
    a0 = a_ok ? *(const float4*)(Ap)     : z4;
    a1 = a_ok ? *(const float4*)(Ap + 4) : z4;
    b0 = *(const float4*)(Bp);
    b1 = *(const float4*)(Bp + 4);
    {
        float av[8] = {a0.x, a0.y, a0.z, a0.w, a1.x, a1.y, a1.z, a1.w};
#pragma unroll
        for (int j = 0; j < 8; j++) As[0][a_k + j][a_r] = av[j];
        *(float4*)&Bs[0][b_r][b_c]     = b0;
        *(float4*)&Bs[0][b_r][b_c + 4] = b1;
    }
    __syncthreads();

    float acc[8][8];
#pragma unroll
    for (int i = 0; i < 8; i++)
#pragma unroll
        for (int j = 0; j < 8; j++) acc[i][j] = 0.f;

    int niter = K >> 4;
    for (int t = 0; t < niter; t++) {
        int cur = t & 1;
        if (t + 1 < niter) {
            const float* Apn = Ap + (t + 1) * 16;
            const float* Bpn = Bp + (size_t)(t + 1) * 16 * M;
            a0 = a_ok ? *(const float4*)(Apn)     : z4;
            a1 = a_ok ? *(const float4*)(Apn + 4) : z4;
            b0 = *(const float4*)(Bpn);
            b1 = *(const float4*)(Bpn + 4);
        }

#pragma unroll
        for (int kk = 0; kk < 16; kk++) {
            float af[8], bf[8];
#pragma unroll
            for (int i = 0; i < 4; i++) af[i] = As[cur][kk][tr + i];
#pragma unroll
            for (int i = 4; i < 8; i++) af[i] = As[cur][kk][tr + i];
#pragma unroll
            for (int j = 0; j < 8; j++) bf[j] = Bs[cur][kk][tc + j];
#pragma unroll
            for (int i = 0; i < 8; i++)
#pragma unroll
                for (int j = 0; j < 8; j++)
                    acc[i][j] = fmaf(af[i], bf[j], acc[i][j]);
        }

        if (t + 1 < niter) {
            int nxt = cur ^ 1;
            float av[8] = {a0.x, a0.y, a0.z, a0.w, a1.x, a1.y, a1.z, a1.w};
#pragma unroll
            for (int j = 0; j < 8; j++) As[nxt][a_k + j][a_r] = av[j];
            *(float4*)&Bs[nxt][b_r][b_c]     = b0;
            *(float4*)&Bs[nxt][b_r][b_c + 4] = b1;
            __syncthreads();
        }
    }

    // ---- fused attention dots (layer GEMMs only; bias==null, no relu) ----
    if (asrc) {
        float as[8], ad[8];
#pragma unroll
        for (int j = 0; j < 8; j++) { as[j] = asrc[tc + j]; ad[j] = adst[tc + j]; }
        int lane16 = tid & 15;
#pragma unroll
        for (int i = 0; i < 8; i++) {
            float ps = 0.f, pd = 0.f;
#pragma unroll
            for (int j = 0; j < 8; j++) {
                ps = fmaf(acc[i][j], as[j], ps);
                pd = fmaf(acc[i][j], ad[j], pd);
            }
#pragma unroll
            for (int o = 8; o > 0; o >>= 1) {
                ps += __shfl_xor_sync(0xffffffffu, ps, o);
                pd += __shfl_xor_sync(0xffffffffu, pd, o);
            }
            if (lane16 == 0) {
                int gr = brow + tr + i;
                if (gr < nrows) { ssrc_out[gr] = ps; sdst_out[gr] = pd; }
            }
        }
    }

#pragma unroll
    for (int i = 0; i < 8; i++) {
        int gr = brow + tr + i;
        if (gr < nrows) {
#pragma unroll
            for (int j = 0; j < 8; j += 4) {
                float4 v = make_float4(acc[i][j], acc[i][j+1], acc[i][j+2], acc[i][j+3]);
                if (bias) {
                    const float4 bb = *(const float4*)(bias + bcol + tc + j);
                    v.x += bb.x; v.y += bb.y; v.z += bb.z; v.w += bb.w;
                }
                if (doRelu) {
                    v.x = fmaxf(v.x, 0.f); v.y = fmaxf(v.y, 0.f);
                    v.z = fmaxf(v.z, 0.f); v.w = fmaxf(v.w, 0.f);
                }
                *(float4*)(C + (size_t)gr * M + bcol + tc + j) = v;
            }
        }
    }
}

// ---------------- warp-per-dst-node segment softmax + weighted aggregate ----
__global__ void gat_agg_k(const float* __restrict__ h,
                          const float* __restrict__ bias,
                          float* __restrict__ out)
{
    int node = blockIdx.x * 8 + (threadIdx.x >> 5);
    int lane = threadIdx.x & 31;
    if (node >= NN) return;

    int beg = g_offs[node], end = g_offs[node + 1];
    float sd = g_sdst[node];

    // pass 1: online softmax (max + sum in one sweep)
    float mx = -3.4e38f, sum = 0.f;
    for (int e = beg + lane; e < end; e += 32) {
        float sc = g_ssrc[g_srcs[e]] + sd;
        sc = sc > 0.f ? sc : 0.2f * sc;
        float m2 = fmaxf(mx, sc);
        sum = sum * __expf(mx - m2) + __expf(sc - m2);
        mx = m2;
    }
    float wm = mx;
#pragma unroll
    for (int o = 16; o > 0; o >>= 1)
        wm = fmaxf(wm, __shfl_xor_sync(0xffffffffu, wm, o));
    sum *= __expf(mx - wm);
#pragma unroll
    for (int o = 16; o > 0; o >>= 1)
        sum += __shfl_xor_sync(0xffffffffu, sum, o);
    float inv = 1.f / sum;

    // pass 2: weighted row aggregation (full warp per edge, 4 floats/lane)
    float4 acc = make_float4(0.f, 0.f, 0.f, 0.f);
    for (int e = beg; e < end; e++) {
        int sv = g_srcs[e];
        float sc = g_ssrc[sv] + sd;            // broadcast L1 hit
        sc = sc > 0.f ? sc : 0.2f * sc;
        float w = __expf(sc - wm) * inv;
        float4 hv = *(const float4*)(h + (size_t)sv * DD + lane * 4);
        acc.x = fmaf(hv.x, w, acc.x);
        acc.y = fmaf(hv.y, w, acc.y);
        acc.z = fmaf(hv.z, w, acc.z);
        acc.w = fmaf(hv.w, w, acc.w);
    }

    float4 bv = *(const float4*)(bias + lane * 4);
    acc.x = fmaxf(acc.x + bv.x, 0.f);
    acc.y = fmaxf(acc.y + bv.y, 0.f);
    acc.z = fmaxf(acc.z + bv.z, 0.f);
    acc.w = fmaxf(acc.w + bv.w, 0.f);
    *(float4*)(out + (size_t)node * DD + lane * 4) = acc;
}

// ---------------- final tiny GEMM: out[N,6] = hid[N,256] @ Wm2 + bm2 --------
__global__ void mlp2_k(const float* __restrict__ hid,
                       const float* __restrict__ W,
                       const float* __restrict__ b,
                       float* __restrict__ out)
{
    int node = blockIdx.x * 8 + (threadIdx.x >> 5);
    int lane = threadIdx.x & 31;
    if (node >= NN) return;
    float acc[CC];
#pragma unroll
    for (int c = 0; c < CC; c++) acc[c] = 0.f;
#pragma unroll
    for (int i = 0; i < HH / 32; i++) {
        int k = lane + i * 32;
        float v = hid[(size_t)node * HH + k];
#pragma unroll
        for (int c = 0; c < CC; c++)
            acc[c] = fmaf(v, W[k * CC + c], acc[c]);
    }
#pragma unroll
    for (int c = 0; c < CC; c++) {
#pragma unroll
        for (int o = 16; o > 0; o >>= 1)
            acc[c] += __shfl_xor_sync(0xffffffffu, acc[c], o);
    }
    if (lane == 0) {
#pragma unroll
        for (int c = 0; c < CC; c++)
            out[(size_t)node * CC + c] = acc[c] + b[c];
    }
}

// ---------------- host launch ------------------------------------------------
static void* symaddr(const void* s) {
    void* p = nullptr;
    cudaGetSymbolAddress(&p, s);
    return p;
}

extern "C" void kernel_launch(void* const* d_in, const int* in_sizes, int n_in,
                              void* d_out, int out_size)
{
    const float* x   = (const float*)d_in[0];
    const void*  ei  = d_in[1];
    const float* W[3]  = { (const float*)d_in[2],  (const float*)d_in[6],  (const float*)d_in[10] };
    const float* b[3]  = { (const float*)d_in[3],  (const float*)d_in[7],  (const float*)d_in[11] };
    const float* as_[3]= { (const float*)d_in[4],  (const float*)d_in[8],  (const float*)d_in[12] };
    const float* ad_[3]= { (const float*)d_in[5],  (const float*)d_in[9],  (const float*)d_in[13] };
    const float* Wm1 = (const float*)d_in[14];
    const float* bm1 = (const float*)d_in[15];
    const float* Wm2 = (const float*)d_in[16];
    const float* bm2 = (const float*)d_in[17];
    float* out = (float*)d_out;

    float* h0  = (float*)symaddr(g_h0);
    float* h1  = (float*)symaddr(g_h1);
    float* hid = (float*)symaddr(g_hid);
    float* ssrc = (float*)symaddr(g_ssrc);
    float* sdst = (float*)symaddr(g_sdst);

    // ---- graph preprocessing (shared by all 3 layers) ----
    detect_k<<<1, 256>>>((const unsigned int*)ei);
    init_k<<<(NN + 255) / 256, 256>>>();
    build_k<<<(ET + 255) / 256, 256>>>(ei);
    scan1_k<<<NB, 1024>>>();
    scan2_k<<<1, 32>>>();
    scan3_k<<<(NN + 255) / 256, 256>>>();
    scatter_k<<<(ET + 255) / 256, 256>>>();

    // ---- 3 GAT layers (attention dots fused into GEMM epilogue) ----
    const float* cur = x;
    for (int l = 0; l < 3; l++) {
        sgemm_k<<<dim3((NN + 127) / 128, 1), 256>>>(
            cur, W[l], nullptr, h0, NN, DD, DD, 0,
            as_[l], ad_[l], ssrc, sdst);
        gat_agg_k<<<(NN + 7) / 8, 256>>>(h0, b[l], h1);
        cur = h1;
    }

    // ---- MLP head ----
    sgemm_k<<<dim3((NN + 127) / 128, 2), 256>>>(
        h1, Wm1, bm1, hid, NN, DD, HH, 1,
        nullptr, nullptr, nullptr, nullptr);
    mlp2_k<<<(NN + 7) / 8, 256>>>(hid, Wm2, bm2, out);
}

// round 7
// speedup vs baseline: 1.2254x; 1.0772x over previous
#include <cuda_runtime.h>
#include <cuda_bf16.h>
#include <math.h>

// Problem constants (match reference)
#define NN 50000
#define EE 800000
#define ET (EE + NN)      // edges + self loops = 850000
#define DD 128            // gnn dim
#define HH 256            // mlp hidden
#define CC 6              // labels
#define NB ((NN + 1023) / 1024)   // 49 scan blocks

// ---------------- scratch (device globals; no runtime allocation) -----------
__device__ float g_h0[(size_t)NN * DD];     // projected h (per layer)
__device__ float g_h1[(size_t)NN * DD];     // layer output / next input
__device__ float g_hid[(size_t)NN * HH];    // mlp hidden
__device__ float g_ssrc[NN];
__device__ float g_sdst[NN];
__device__ float g_ew[ET];                  // cached per-edge leaky-relu score
__device__ int   g_src[ET];
__device__ int   g_dst[ET];
__device__ int   g_srcs[ET];                // src sorted by dst segment
__device__ int   g_deg[NN];
__device__ int   g_offs[NN + 1];            // per-1024-block-local exclusive scan
__device__ int   g_fill[NN];
__device__ int   g_bsum[64];                // block offsets (exclusive)
__device__ int   g_is64;

// ---------------- merged dtype detection + counter init ---------------------
// int64 edge_index => every odd 32-bit word is 0 (values < 50000).
__global__ void detect_init_k(const unsigned int* __restrict__ w) {
    int i = blockIdx.x * blockDim.x + threadIdx.x;
    if (i < NN) { g_deg[i] = 0; g_fill[i] = 0; }
    if (blockIdx.x == 0) {
        __shared__ int any;
        if (threadIdx.x == 0) any = 0;
        __syncthreads();
        int t = 0;
        for (int j = threadIdx.x; j < 1024; j += blockDim.x)
            t |= (w[2 * j + 1] != 0u);
        if (t) any = 1;
        __syncthreads();
        if (threadIdx.x == 0) g_is64 = any ? 0 : 1;
    }
}

// Convert edge list (+ self loops), count in-degrees.
__global__ void build_k(const void* __restrict__ ei) {
    int i = blockIdx.x * blockDim.x + threadIdx.x;
    if (i >= ET) return;
    int s, d;
    if (i < EE) {
        if (g_is64) {
            const long long* p = (const long long*)ei;
            s = (int)p[i]; d = (int)p[EE + i];
        } else {
            const int* p = (const int*)ei;
            s = p[i]; d = p[EE + i];
        }
    } else {
        s = d = i - EE;   // self loop
    }
    g_src[i] = s; g_dst[i] = d;
    atomicAdd(&g_deg[d], 1);
}

// ---------------- 2-phase coalesced scan (block offsets applied by consumers)
// Phase 1: per-block (1024 elems) exclusive scan + block total.
__global__ void scan1_k() {
    __shared__ int wsum[32];
    int b = blockIdx.x, tid = threadIdx.x;
    int i = b * 1024 + tid;
    int v = (i < NN) ? g_deg[i] : 0;
    int lane = tid & 31, wid = tid >> 5;

    int inc = v;
#pragma unroll
    for (int o = 1; o < 32; o <<= 1) {
        int t = __shfl_up_sync(0xffffffffu, inc, o);
        if (lane >= o) inc += t;
    }
    if (lane == 31) wsum[wid] = inc;
    __syncthreads();
    if (wid == 0) {
        int w = wsum[lane];
#pragma unroll
        for (int o = 1; o < 32; o <<= 1) {
            int t = __shfl_up_sync(0xffffffffu, w, o);
            if (lane >= o) w += t;
        }
        wsum[lane] = w;
    }
    __syncthreads();
    int excl = inc - v + (wid ? wsum[wid - 1] : 0);
    if (i < NN) g_offs[i] = excl;            // block-local exclusive prefix
    if (tid == 1023) g_bsum[b] = excl + v;   // block total
}

// Phase 2: single warp turns the 49 block totals into exclusive block offsets.
__global__ void scan2_k() {
    int lane = threadIdx.x;       // 32 threads
    int v0 = (lane < NB) ? g_bsum[lane] : 0;
    int a = v0;
#pragma unroll
    for (int o = 1; o < 32; o <<= 1) {
        int t = __shfl_up_sync(0xffffffffu, a, o);
        if (lane >= o) a += t;
    }
    int tot32 = __shfl_sync(0xffffffffu, a, 31);
    int v1 = (lane + 32 < NB) ? g_bsum[lane + 32] : 0;
    int c = v1;
#pragma unroll
    for (int o = 1; o < 32; o <<= 1) {
        int t = __shfl_up_sync(0xffffffffu, c, o);
        if (lane >= o) c += t;
    }
    g_bsum[lane] = a - v0;                       // exclusive
    g_bsum[lane + 32] = (c - v1) + tot32;
}

__device__ __forceinline__ int seg_off(int i) {
    return (i == NN) ? ET : (g_offs[i] + g_bsum[i >> 10]);
}

// Bucket srcs by dst segment.
__global__ void scatter_k() {
    int i = blockIdx.x * blockDim.x + threadIdx.x;
    if (i >= ET) return;
    int d = g_dst[i];
    int pos = g_offs[d] + g_bsum[d >> 10] + atomicAdd(&g_fill[d], 1);
    g_srcs[pos] = g_src[i];
}

// ---------------- SGEMM: C[nrows,M] = A[nrows,K] @ B[K,M] (+bias, relu) -----
// BM=128, BN=128, BK=8, 256 threads, 8x8 microtile per thread (R4-proven form).
// If asrc != nullptr (layer GEMMs, M==128): fuse per-row attention dots
// ssrc = C·asrc, sdst = C·adst into the epilogue.
__global__ __launch_bounds__(256) void sgemm_k(
    const float* __restrict__ A, const float* __restrict__ B,
    const float* __restrict__ bias, float* __restrict__ C,
    int nrows, int K, int M, int doRelu,
    const float* __restrict__ asrc, const float* __restrict__ adst,
    float* __restrict__ ssrc_out, float* __restrict__ sdst_out)
{
    __shared__ float As[8][128];
    __shared__ float Bs[8][128];
    int brow = blockIdx.x * 128;
    int bcol = blockIdx.y * 128;
    int tid  = threadIdx.x;
    int tr   = (tid / 16) * 8;
    int tc   = (tid % 16) * 8;

    float acc[8][8];
#pragma unroll
    for (int i = 0; i < 8; i++)
#pragma unroll
        for (int j = 0; j < 8; j++) acc[i][j] = 0.f;

    int arow = tid >> 1;          // 0..127
    int akk  = (tid & 1) * 4;     // 0 or 4
    int bkk  = tid >> 5;          // 0..7
    int bcc  = (tid & 31) * 4;    // 0..124

    for (int k0 = 0; k0 < K; k0 += 8) {
        float4 av = make_float4(0.f, 0.f, 0.f, 0.f);
        int gr = brow + arow;
        if (gr < nrows)
            av = *(const float4*)(A + (size_t)gr * K + k0 + akk);
        As[akk + 0][arow] = av.x; As[akk + 1][arow] = av.y;
        As[akk + 2][arow] = av.z; As[akk + 3][arow] = av.w;

        float4 bv = *(const float4*)(B + (size_t)(k0 + bkk) * M + bcol + bcc);
        *(float4*)&Bs[bkk][bcc] = bv;
        __syncthreads();

#pragma unroll
        for (int kk = 0; kk < 8; kk++) {
            float af[8], bf[8];
#pragma unroll
            for (int i = 0; i < 8; i++) af[i] = As[kk][tr + i];
#pragma unroll
            for (int j = 0; j < 8; j++) bf[j] = Bs[kk][tc + j];
#pragma unroll
            for (int i = 0; i < 8; i++)
#pragma unroll
                for (int j = 0; j < 8; j++)
                    acc[i][j] = fmaf(af[i], bf[j], acc[i][j]);
        }
        __syncthreads();
    }

    // ---- fused attention dots (layer GEMMs only; bias==null, no relu) ----
    if (asrc) {
        float as[8], ad[8];
#pragma unroll
        for (int j = 0; j < 8; j++) { as[j] = asrc[tc + j]; ad[j] = adst[tc + j]; }
        int lane16 = tid & 15;
#pragma unroll
        for (int i = 0; i < 8; i++) {
            float ps = 0.f, pd = 0.f;
#pragma unroll
            for (int j = 0; j < 8; j++) {
                ps = fmaf(acc[i][j], as[j], ps);
                pd = fmaf(acc[i][j], ad[j], pd);
            }
#pragma unroll
            for (int o = 8; o > 0; o >>= 1) {
                ps += __shfl_xor_sync(0xffffffffu, ps, o);
                pd += __shfl_xor_sync(0xffffffffu, pd, o);
            }
            if (lane16 == 0) {
                int gr = brow + tr + i;
                if (gr < nrows) { ssrc_out[gr] = ps; sdst_out[gr] = pd; }
            }
        }
    }

#pragma unroll
    for (int i = 0; i < 8; i++) {
        int gr = brow + tr + i;
        if (gr < nrows) {
#pragma unroll
            for (int j = 0; j < 8; j += 4) {
                float4 v = make_float4(acc[i][j], acc[i][j+1], acc[i][j+2], acc[i][j+3]);
                if (bias) {
                    const float4 bb = *(const float4*)(bias + bcol + tc + j);
                    v.x += bb.x; v.y += bb.y; v.z += bb.z; v.w += bb.w;
                }
                if (doRelu) {
                    v.x = fmaxf(v.x, 0.f); v.y = fmaxf(v.y, 0.f);
                    v.z = fmaxf(v.z, 0.f); v.w = fmaxf(v.w, 0.f);
                }
                *(float4*)(C + (size_t)gr * M + bcol + tc + j) = v;
            }
        }
    }
}

// ---------------- warp-per-dst-node segment softmax + weighted aggregate ----
__global__ void gat_agg_k(const float* __restrict__ h,
                          const float* __restrict__ bias,
                          float* __restrict__ out)
{
    int node = blockIdx.x * 8 + (threadIdx.x >> 5);
    int lane = threadIdx.x & 31;
    if (node >= NN) return;

    int beg = seg_off(node), end = seg_off(node + 1);
    float sd = g_sdst[node];

    // pass 1: online softmax (max + sum in one sweep); cache score per edge
    float mx = -3.4e38f, sum = 0.f;
    for (int e = beg + lane; e < end; e += 32) {
        float sc = g_ssrc[g_srcs[e]] + sd;
        sc = sc > 0.f ? sc : 0.2f * sc;
        g_ew[e] = sc;                       // coalesced-ish cache write
        float m2 = fmaxf(mx, sc);
        sum = sum * __expf(mx - m2) + __expf(sc - m2);
        mx = m2;
    }
    float wm = mx;
#pragma unroll
    for (int o = 16; o > 0; o >>= 1)
        wm = fmaxf(wm, __shfl_xor_sync(0xffffffffu, wm, o));
    sum *= __expf(mx - wm);
#pragma unroll
    for (int o = 16; o > 0; o >>= 1)
        sum += __shfl_xor_sync(0xffffffffu, sum, o);
    float inv = 1.f / sum;

    // pass 2: weighted row aggregation (full warp per edge, 4 floats/lane)
    float4 acc = make_float4(0.f, 0.f, 0.f, 0.f);
    for (int e = beg; e < end; e++) {
        int sv = g_srcs[e];
        float w = __expf(g_ew[e] - wm) * inv;  // broadcast L1 hit
        float4 hv = *(const float4*)(h + (size_t)sv * DD + lane * 4);
        acc.x = fmaf(hv.x, w, acc.x);
        acc.y = fmaf(hv.y, w, acc.y);
        acc.z = fmaf(hv.z, w, acc.z);
        acc.w = fmaf(hv.w, w, acc.w);
    }

    float4 bv = *(const float4*)(bias + lane * 4);
    acc.x = fmaxf(acc.x + bv.x, 0.f);
    acc.y = fmaxf(acc.y + bv.y, 0.f);
    acc.z = fmaxf(acc.z + bv.z, 0.f);
    acc.w = fmaxf(acc.w + bv.w, 0.f);
    *(float4*)(out + (size_t)node * DD + lane * 4) = acc;
}

// ---------------- final tiny GEMM: out[N,6] = hid[N,256] @ Wm2 + bm2 --------
__global__ void mlp2_k(const float* __restrict__ hid,
                       const float* __restrict__ W,
                       const float* __restrict__ b,
                       float* __restrict__ out)
{
    int node = blockIdx.x * 8 + (threadIdx.x >> 5);
    int lane = threadIdx.x & 31;
    if (node >= NN) return;
    float acc[CC];
#pragma unroll
    for (int c = 0; c < CC; c++) acc[c] = 0.f;
#pragma unroll
    for (int i = 0; i < HH / 32; i++) {
        int k = lane + i * 32;
        float v = hid[(size_t)node * HH + k];
#pragma unroll
        for (int c = 0; c < CC; c++)
            acc[c] = fmaf(v, W[k * CC + c], acc[c]);
    }
#pragma unroll
    for (int c = 0; c < CC; c++) {
#pragma unroll
        for (int o = 16; o > 0; o >>= 1)
            acc[c] += __shfl_xor_sync(0xffffffffu, acc[c], o);
    }
    if (lane == 0) {
#pragma unroll
        for (int c = 0; c < CC; c++)
            out[(size_t)node * CC + c] = acc[c] + b[c];
    }
}

// ---------------- host launch ------------------------------------------------
static void* symaddr(const void* s) {
    void* p = nullptr;
    cudaGetSymbolAddress(&p, s);
    return p;
}

extern "C" void kernel_launch(void* const* d_in, const int* in_sizes, int n_in,
                              void* d_out, int out_size)
{
    const float* x   = (const float*)d_in[0];
    const void*  ei  = d_in[1];
    const float* W[3]  = { (const float*)d_in[2],  (const float*)d_in[6],  (const float*)d_in[10] };
    const float* b[3]  = { (const float*)d_in[3],  (const float*)d_in[7],  (const float*)d_in[11] };
    const float* as_[3]= { (const float*)d_in[4],  (const float*)d_in[8],  (const float*)d_in[12] };
    const float* ad_[3]= { (const float*)d_in[5],  (const float*)d_in[9],  (const float*)d_in[13] };
    const float* Wm1 = (const float*)d_in[14];
    const float* bm1 = (const float*)d_in[15];
    const float* Wm2 = (const float*)d_in[16];
    const float* bm2 = (const float*)d_in[17];
    float* out = (float*)d_out;

    float* h0  = (float*)symaddr(g_h0);
    float* h1  = (float*)symaddr(g_h1);
    float* hid = (float*)symaddr(g_hid);
    float* ssrc = (float*)symaddr(g_ssrc);
    float* sdst = (float*)symaddr(g_sdst);

    // ---- graph preprocessing (launch indices 0..4; sgemm lands at 5 = ncu -s 5)
    detect_init_k<<<(NN + 255) / 256, 256>>>((const unsigned int*)ei);
    build_k<<<(ET + 255) / 256, 256>>>(ei);
    scan1_k<<<NB, 1024>>>();
    scan2_k<<<1, 32>>>();
    scatter_k<<<(ET + 255) / 256, 256>>>();

    // ---- 3 GAT layers (attention dots fused into GEMM epilogue) ----
    const float* cur = x;
    for (int l = 0; l < 3; l++) {
        sgemm_k<<<dim3((NN + 127) / 128, 1), 256>>>(
            cur, W[l], nullptr, h0, NN, DD, DD, 0,
            as_[l], ad_[l], ssrc, sdst);
        gat_agg_k<<<(NN + 7) / 8, 256>>>(h0, b[l], h1);
        cur = h1;
    }

    // ---- MLP head ----
    sgemm_k<<<dim3((NN + 127) / 128, 2), 256>>>(
        h1, Wm1, bm1, hid, NN, DD, HH, 1,
        nullptr, nullptr, nullptr, nullptr);
    mlp2_k<<<(NN + 7) / 8, 256>>>(hid, Wm2, bm2, out);
}

// round 8
// speedup vs baseline: 1.5892x; 1.2969x over previous
#include <cuda_runtime.h>
#include <cuda_bf16.h>
#include <math.h>

// Problem constants (match reference)
#define NN 50000
#define EE 800000
#define ET (EE + NN)      // edges + self loops = 850000
#define DD 128            // gnn dim (all GEMM K = 128)
#define HH 256            // mlp hidden
#define CC 6              // labels
#define NB ((NN + 1023) / 1024)   // 49 scan blocks

// ---------------- scratch (device globals; no runtime allocation) -----------
__device__ float g_h0[(size_t)NN * DD];     // projected h (per layer)
__device__ float g_h1[(size_t)NN * DD];     // layer output / next input
__device__ float g_hid[(size_t)NN * HH];    // mlp hidden
__device__ float g_ssrc[NN];
__device__ float g_sdst[NN];
__device__ float g_ew[ET];                  // cached per-edge leaky-relu score
__device__ int   g_src[ET];
__device__ int   g_dst[ET];
__device__ int   g_srcs[ET];                // src sorted by dst segment
__device__ int   g_deg[NN];
__device__ int   g_offs[NN + 1];            // per-1024-block-local exclusive scan
__device__ int   g_fill[NN];
__device__ int   g_bsum[64];                // block offsets (exclusive)
__device__ int   g_is64;

// ---------------- merged dtype detection + counter init ---------------------
// int64 edge_index => every odd 32-bit word is 0 (values < 50000).
__global__ void detect_init_k(const unsigned int* __restrict__ w) {
    int i = blockIdx.x * blockDim.x + threadIdx.x;
    if (i < NN) { g_deg[i] = 0; g_fill[i] = 0; }
    if (blockIdx.x == 0) {
        __shared__ int any;
        if (threadIdx.x == 0) any = 0;
        __syncthreads();
        int t = 0;
        for (int j = threadIdx.x; j < 1024; j += blockDim.x)
            t |= (w[2 * j + 1] != 0u);
        if (t) any = 1;
        __syncthreads();
        if (threadIdx.x == 0) g_is64 = any ? 0 : 1;
    }
}

// Convert edge list (+ self loops), count in-degrees.
__global__ void build_k(const void* __restrict__ ei) {
    int i = blockIdx.x * blockDim.x + threadIdx.x;
    if (i >= ET) return;
    int s, d;
    if (i < EE) {
        if (g_is64) {
            const long long* p = (const long long*)ei;
            s = (int)p[i]; d = (int)p[EE + i];
        } else {
            const int* p = (const int*)ei;
            s = p[i]; d = p[EE + i];
        }
    } else {
        s = d = i - EE;   // self loop
    }
    g_src[i] = s; g_dst[i] = d;
    atomicAdd(&g_deg[d], 1);
}

// ---------------- 2-phase coalesced scan (block offsets applied by consumers)
__global__ void scan1_k() {
    __shared__ int wsum[32];
    int b = blockIdx.x, tid = threadIdx.x;
    int i = b * 1024 + tid;
    int v = (i < NN) ? g_deg[i] : 0;
    int lane = tid & 31, wid = tid >> 5;

    int inc = v;
#pragma unroll
    for (int o = 1; o < 32; o <<= 1) {
        int t = __shfl_up_sync(0xffffffffu, inc, o);
        if (lane >= o) inc += t;
    }
    if (lane == 31) wsum[wid] = inc;
    __syncthreads();
    if (wid == 0) {
        int w = wsum[lane];
#pragma unroll
        for (int o = 1; o < 32; o <<= 1) {
            int t = __shfl_up_sync(0xffffffffu, w, o);
            if (lane >= o) w += t;
        }
        wsum[lane] = w;
    }
    __syncthreads();
    int excl = inc - v + (wid ? wsum[wid - 1] : 0);
    if (i < NN) g_offs[i] = excl;            // block-local exclusive prefix
    if (tid == 1023) g_bsum[b] = excl + v;   // block total
}

__global__ void scan2_k() {
    int lane = threadIdx.x;       // 32 threads
    int v0 = (lane < NB) ? g_bsum[lane] : 0;
    int a = v0;
#pragma unroll
    for (int o = 1; o < 32; o <<= 1) {
        int t = __shfl_up_sync(0xffffffffu, a, o);
        if (lane >= o) a += t;
    }
    int tot32 = __shfl_sync(0xffffffffu, a, 31);
    int v1 = (lane + 32 < NB) ? g_bsum[lane + 32] : 0;
    int c = v1;
#pragma unroll
    for (int o = 1; o < 32; o <<= 1) {
        int t = __shfl_up_sync(0xffffffffu, c, o);
        if (lane >= o) c += t;
    }
    g_bsum[lane] = a - v0;                       // exclusive
    g_bsum[lane + 32] = (c - v1) + tot32;
}

__device__ __forceinline__ int seg_off(int i) {
    return (i == NN) ? ET : (g_offs[i] + g_bsum[i >> 10]);
}

// Bucket srcs by dst segment.
__global__ void scatter_k() {
    int i = blockIdx.x * blockDim.x + threadIdx.x;
    if (i >= ET) return;
    int d = g_dst[i];
    int pos = g_offs[d] + g_bsum[d >> 10] + atomicAdd(&g_fill[d], 1);
    g_srcs[pos] = g_src[i];
}

// ---------------- tf32x3 tensor-core GEMM -----------------------------------
// C[nrows, M] = A[nrows, 128] @ B[128, M] (+bias, relu). K fixed = 128.
// Block tile 128x128, 256 threads, 8 warps as 4(m) x 2(n); warp tile 32x64.
// mma.sync.m16n8k8.tf32 with 3xTF32 split (hi*hi + hi*lo + lo*hi).
// If asrc != nullptr (layer GEMMs, M==128): fuse ssrc = C*asrc, sdst = C*adst.

__device__ __forceinline__ unsigned f2tf(float x) {
    unsigned r;
    asm("cvt.rna.tf32.f32 %0, %1;" : "=r"(r) : "f"(x));
    return r;
}
__device__ __forceinline__ void split_tf(float x, unsigned& hi, unsigned& lo) {
    hi = f2tf(x);
    lo = f2tf(x - __uint_as_float(hi));
}
__device__ __forceinline__ void mma_tf32(float c[4],
    unsigned a0, unsigned a1, unsigned a2, unsigned a3,
    unsigned b0, unsigned b1)
{
    asm volatile(
        "mma.sync.aligned.m16n8k8.row.col.f32.tf32.tf32.f32 "
        "{%0,%1,%2,%3}, {%4,%5,%6,%7}, {%8,%9}, {%0,%1,%2,%3};"
        : "+f"(c[0]), "+f"(c[1]), "+f"(c[2]), "+f"(c[3])
        : "r"(a0), "r"(a1), "r"(a2), "r"(a3), "r"(b0), "r"(b1));
}

__global__ __launch_bounds__(256) void sgemm_k(
    const float* __restrict__ A, const float* __restrict__ B,
    const float* __restrict__ bias, float* __restrict__ C,
    int nrows, int M, int doRelu,
    const float* __restrict__ asrc, const float* __restrict__ adst,
    float* __restrict__ ssrc_out, float* __restrict__ sdst_out)
{
    __shared__ float As[128][36];    // [m][k], stride 36: conflict-free frags
    __shared__ float Bs[32][136];    // [k][n], stride 136: conflict-free frags
    __shared__ float sdots[128][2];

    int tid  = threadIdx.x;
    int lane = tid & 31, w = tid >> 5;
    int g = lane >> 2, tg = lane & 3;
    int wm = w & 3, wn = w >> 2;          // warp grid 4(m) x 2(n)
    int m0 = wm * 32, n0 = wn * 64;
    int brow = blockIdx.x * 128;
    int bcol = blockIdx.y * 128;

    if (tid < 128) { sdots[tid][0] = 0.f; sdots[tid][1] = 0.f; }

    float Cacc[2][8][4];
#pragma unroll
    for (int ma = 0; ma < 2; ma++)
#pragma unroll
        for (int na = 0; na < 8; na++)
#pragma unroll
            for (int q = 0; q < 4; q++) Cacc[ma][na][q] = 0.f;

    int ar = tid >> 3;            // 0..31 (A load row group)
    int ak = (tid & 7) * 4;       // 0..28
    int bk = tid >> 5;            // 0..7  (B load k group)
    int bn = (tid & 31) * 4;      // 0..124

    const float4 z4 = make_float4(0.f, 0.f, 0.f, 0.f);

    for (int c = 0; c < 4; c++) {
        int k0 = c * 32;
        __syncthreads();
#pragma unroll
        for (int i = 0; i < 4; i++) {
            int r = ar + 32 * i;
            int grow = brow + r;
            float4 v = (grow < nrows)
                ? *(const float4*)(A + (size_t)grow * 128 + k0 + ak) : z4;
            *(float4*)&As[r][ak] = v;
        }
#pragma unroll
        for (int i = 0; i < 4; i++) {
            int kr = bk + 8 * i;
            float4 v = *(const float4*)(B + (size_t)(k0 + kr) * M + bcol + bn);
            *(float4*)&Bs[kr][bn] = v;
        }
        __syncthreads();

#pragma unroll
        for (int ks = 0; ks < 4; ks++) {
            int kk = ks * 8;
            unsigned ahi[2][4], alo[2][4];
#pragma unroll
            for (int ma = 0; ma < 2; ma++) {
                int r0 = m0 + ma * 16 + g;
                split_tf(As[r0][kk + tg],         ahi[ma][0], alo[ma][0]);
                split_tf(As[r0 + 8][kk + tg],     ahi[ma][1], alo[ma][1]);
                split_tf(As[r0][kk + tg + 4],     ahi[ma][2], alo[ma][2]);
                split_tf(As[r0 + 8][kk + tg + 4], ahi[ma][3], alo[ma][3]);
            }
#pragma unroll
            for (int half = 0; half < 2; half++) {
                unsigned bhi[4][2], blo[4][2];
#pragma unroll
                for (int j = 0; j < 4; j++) {
                    int cn = n0 + (half * 4 + j) * 8 + g;
                    split_tf(Bs[kk + tg][cn],     bhi[j][0], blo[j][0]);
                    split_tf(Bs[kk + tg + 4][cn], bhi[j][1], blo[j][1]);
                }
#pragma unroll
                for (int ma = 0; ma < 2; ma++)
#pragma unroll
                    for (int j = 0; j < 4; j++) {
                        float* cc = Cacc[ma][half * 4 + j];
                        mma_tf32(cc, ahi[ma][0], ahi[ma][1], ahi[ma][2], ahi[ma][3],
                                     bhi[j][0], bhi[j][1]);
                        mma_tf32(cc, ahi[ma][0], ahi[ma][1], ahi[ma][2], ahi[ma][3],
                                     blo[j][0], blo[j][1]);
                        mma_tf32(cc, alo[ma][0], alo[ma][1], alo[ma][2], alo[ma][3],
                                     bhi[j][0], bhi[j][1]);
                    }
            }
        }
    }

    // ---- fused attention dots (layer GEMMs only: M==128, bcol==0) ----
    if (asrc) {
#pragma unroll
        for (int ma = 0; ma < 2; ma++) {
            float ps0 = 0.f, pd0 = 0.f, ps1 = 0.f, pd1 = 0.f;
#pragma unroll
            for (int na = 0; na < 8; na++) {
                int cn = n0 + na * 8 + tg * 2;
                float a0v = asrc[cn], a1v = asrc[cn + 1];
                float d0v = adst[cn], d1v = adst[cn + 1];
                float* cc = Cacc[ma][na];
                ps0 += cc[0] * a0v + cc[1] * a1v;
                pd0 += cc[0] * d0v + cc[1] * d1v;
                ps1 += cc[2] * a0v + cc[3] * a1v;
                pd1 += cc[2] * d0v + cc[3] * d1v;
            }
#pragma unroll
            for (int o = 1; o < 4; o <<= 1) {
                ps0 += __shfl_xor_sync(0xffffffffu, ps0, o);
                pd0 += __shfl_xor_sync(0xffffffffu, pd0, o);
                ps1 += __shfl_xor_sync(0xffffffffu, ps1, o);
                pd1 += __shfl_xor_sync(0xffffffffu, pd1, o);
            }
            if (tg == 0) {
                int r0 = m0 + ma * 16 + g;
                atomicAdd(&sdots[r0][0], ps0);
                atomicAdd(&sdots[r0][1], pd0);
                atomicAdd(&sdots[r0 + 8][0], ps1);
                atomicAdd(&sdots[r0 + 8][1], pd1);
            }
        }
    }

    // ---- global stores ----
#pragma unroll
    for (int ma = 0; ma < 2; ma++) {
        int r0 = brow + m0 + ma * 16 + g;
#pragma unroll
        for (int na = 0; na < 8; na++) {
            int cn = bcol + n0 + na * 8 + tg * 2;
            float* cc = Cacc[ma][na];
            float v0 = cc[0], v1 = cc[1], v2 = cc[2], v3 = cc[3];
            if (bias) {
                float b0 = bias[cn], b1 = bias[cn + 1];
                v0 += b0; v1 += b1; v2 += b0; v3 += b1;
            }
            if (doRelu) {
                v0 = fmaxf(v0, 0.f); v1 = fmaxf(v1, 0.f);
                v2 = fmaxf(v2, 0.f); v3 = fmaxf(v3, 0.f);
            }
            if (r0 < nrows)     *(float2*)(C + (size_t)r0 * M + cn)       = make_float2(v0, v1);
            if (r0 + 8 < nrows) *(float2*)(C + (size_t)(r0 + 8) * M + cn) = make_float2(v2, v3);
        }
    }

    if (asrc) {
        __syncthreads();
        if (tid < 128) {
            int gr = brow + tid;
            if (gr < nrows) {
                ssrc_out[gr] = sdots[tid][0];
                sdst_out[gr] = sdots[tid][1];
            }
        }
    }
}

// ---------------- warp-per-dst-node segment softmax + weighted aggregate ----
__global__ void gat_agg_k(const float* __restrict__ h,
                          const float* __restrict__ bias,
                          float* __restrict__ out)
{
    int node = blockIdx.x * 8 + (threadIdx.x >> 5);
    int lane = threadIdx.x & 31;
    if (node >= NN) return;

    int beg = seg_off(node), end = seg_off(node + 1);
    float sd = g_sdst[node];

    // pass 1: online softmax (max + sum in one sweep); cache score per edge
    float mx = -3.4e38f, sum = 0.f;
    for (int e = beg + lane; e < end; e += 32) {
        float sc = g_ssrc[g_srcs[e]] + sd;
        sc = sc > 0.f ? sc : 0.2f * sc;
        g_ew[e] = sc;
        float m2 = fmaxf(mx, sc);
        sum = sum * __expf(mx - m2) + __expf(sc - m2);
        mx = m2;
    }
    float wm = mx;
#pragma unroll
    for (int o = 16; o > 0; o >>= 1)
        wm = fmaxf(wm, __shfl_xor_sync(0xffffffffu, wm, o));
    sum *= __expf(mx - wm);
#pragma unroll
    for (int o = 16; o > 0; o >>= 1)
        sum += __shfl_xor_sync(0xffffffffu, sum, o);
    float inv = 1.f / sum;

    // pass 2: weighted row aggregation (full warp per edge, 4 floats/lane)
    float4 acc = make_float4(0.f, 0.f, 0.f, 0.f);
    for (int e = beg; e < end; e++) {
        int sv = g_srcs[e];
        float w = __expf(g_ew[e] - wm) * inv;
        float4 hv = *(const float4*)(h + (size_t)sv * DD + lane * 4);
        acc.x = fmaf(hv.x, w, acc.x);
        acc.y = fmaf(hv.y, w, acc.y);
        acc.z = fmaf(hv.z, w, acc.z);
        acc.w = fmaf(hv.w, w, acc.w);
    }

    float4 bv = *(const float4*)(bias + lane * 4);
    acc.x = fmaxf(acc.x + bv.x, 0.f);
    acc.y = fmaxf(acc.y + bv.y, 0.f);
    acc.z = fmaxf(acc.z + bv.z, 0.f);
    acc.w = fmaxf(acc.w + bv.w, 0.f);
    *(float4*)(out + (size_t)node * DD + lane * 4) = acc;
}

// ---------------- final tiny GEMM: out[N,6] = hid[N,256] @ Wm2 + bm2 --------
__global__ void mlp2_k(const float* __restrict__ hid,
                       const float* __restrict__ W,
                       const float* __restrict__ b,
                       float* __restrict__ out)
{
    int node = blockIdx.x * 8 + (threadIdx.x >> 5);
    int lane = threadIdx.x & 31;
    if (node >= NN) return;
    float acc[CC];
#pragma unroll
    for (int c = 0; c < CC; c++) acc[c] = 0.f;
#pragma unroll
    for (int i = 0; i < HH / 32; i++) {
        int k = lane + i * 32;
        float v = hid[(size_t)node * HH + k];
#pragma unroll
        for (int c = 0; c < CC; c++)
            acc[c] = fmaf(v, W[k * CC + c], acc[c]);
    }
#pragma unroll
    for (int c = 0; c < CC; c++) {
#pragma unroll
        for (int o = 16; o > 0; o >>= 1)
            acc[c] += __shfl_xor_sync(0xffffffffu, acc[c], o);
    }
    if (lane == 0) {
#pragma unroll
        for (int c = 0; c < CC; c++)
            out[(size_t)node * CC + c] = acc[c] + b[c];
    }
}

// ---------------- host launch ------------------------------------------------
static void* symaddr(const void* s) {
    void* p = nullptr;
    cudaGetSymbolAddress(&p, s);
    return p;
}

extern "C" void kernel_launch(void* const* d_in, const int* in_sizes, int n_in,
                              void* d_out, int out_size)
{
    const float* x   = (const float*)d_in[0];
    const void*  ei  = d_in[1];
    const float* W[3]  = { (const float*)d_in[2],  (const float*)d_in[6],  (const float*)d_in[10] };
    const float* b[3]  = { (const float*)d_in[3],  (const float*)d_in[7],  (const float*)d_in[11] };
    const float* as_[3]= { (const float*)d_in[4],  (const float*)d_in[8],  (const float*)d_in[12] };
    const float* ad_[3]= { (const float*)d_in[5],  (const float*)d_in[9],  (const float*)d_in[13] };
    const float* Wm1 = (const float*)d_in[14];
    const float* bm1 = (const float*)d_in[15];
    const float* Wm2 = (const float*)d_in[16];
    const float* bm2 = (const float*)d_in[17];
    float* out = (float*)d_out;

    float* h0  = (float*)symaddr(g_h0);
    float* h1  = (float*)symaddr(g_h1);
    float* hid = (float*)symaddr(g_hid);
    float* ssrc = (float*)symaddr(g_ssrc);
    float* sdst = (float*)symaddr(g_sdst);

    // ---- graph preprocessing (launch idx 0..4; first sgemm = idx 5 = ncu -s 5)
    detect_init_k<<<(NN + 255) / 256, 256>>>((const unsigned int*)ei);
    build_k<<<(ET + 255) / 256, 256>>>(ei);
    scan1_k<<<NB, 1024>>>();
    scan2_k<<<1, 32>>>();
    scatter_k<<<(ET + 255) / 256, 256>>>();

    // ---- 3 GAT layers (attention dots fused into GEMM epilogue) ----
    const float* cur = x;
    for (int l = 0; l < 3; l++) {
        sgemm_k<<<dim3((NN + 127) / 128, 1), 256>>>(
            cur, W[l], nullptr, h0, NN, DD, 0,
            as_[l], ad_[l], ssrc, sdst);
        gat_agg_k<<<(NN + 7) / 8, 256>>>(h0, b[l], h1);
        cur = h1;
    }

    // ---- MLP head ----
    sgemm_k<<<dim3((NN + 127) / 128, 2), 256>>>(
        h1, Wm1, bm1, hid, NN, HH, 1,
        nullptr, nullptr, nullptr, nullptr);
    mlp2_k<<<(NN + 7) / 8, 256>>>(hid, Wm2, bm2, out);
}